// round 1
// baseline (speedup 1.0000x reference)
#include <cuda_runtime.h>
#include <math.h>

// ---------------- static problem config ----------------
#define BNN   8192      // total nodes (8*1024)
#define CC    64        // channels
#define KSEL  11        // K+1 neighbors
#define NLOC  1568      // 8 * 196 local hyperedges
#define NROWS 1024      // nodes per sample (32*32)

// ---------------- device scratch (no allocations allowed) ----------------
__device__ float g_dists[(size_t)BNN * BNN];   // 256 MB distance matrix
__device__ float g_u[BNN * CC];                // dv2[i] * (x W^T + b)
__device__ float g_sq[BNN];                    // row squared norms
__device__ int   g_inds[BNN * KSEL];           // top-11 neighbor indices
__device__ int   g_de[BNN];                    // KNN edge degrees
__device__ float g_sknn[BNN * CC];             // KNN edge sums (later scaled by 1/DE)
__device__ float g_sloc[NLOC * CC];            // local edge sums / 25
__device__ float g_z[BNN * CC];                // aggregated features
__device__ float g_stats[2 * CC];              // per-channel sum / sumsq

// ---------------- helpers ----------------
__device__ __forceinline__ int covdim(int r) {
    // number of even window starts s in [max(0,r-4), min(26,r)]
    int lo = r - 4; if (lo < 0) lo = 0;
    int hi = r;     if (hi > 26) hi = 26;
    if (hi < lo) return 0;
    return hi / 2 - (lo + 1) / 2 + 1;
}

__device__ __forceinline__ float dv2f(int node) {
    int ln = node & (NROWS - 1);
    int r = ln >> 5, c = ln & 31;
    int deg = covdim(r) * covdim(c);
    return 1.0f / sqrtf((float)(KSEL + deg));
}

// ---------------- kZero: clear accumulators ----------------
__global__ void kZero() {
    int i = blockIdx.x * 256 + threadIdx.x;   // grid 2048 -> 524288 threads
    if (i < BNN * CC) g_sknn[i] = 0.0f;
    if (i < BNN)      g_de[i]   = 0;
    if (i < 2 * CC)   g_stats[i] = 0.0f;
}

// ---------------- kA: sq norms + u = dv2 * (x W^T + b) ----------------
__global__ __launch_bounds__(256) void kA(const float* __restrict__ x,
                                          const float* __restrict__ W,
                                          const float* __restrict__ bconv) {
    __shared__ float Ws[CC][CC + 1];
    __shared__ float xs[4][CC];
    __shared__ float red[256];
    int tid = threadIdx.x;
    int node0 = blockIdx.x * 4;

    for (int i = tid; i < CC * CC; i += 256) Ws[i >> 6][i & 63] = W[i];
    for (int i = tid; i < 4 * CC; i += 256) xs[i >> 6][i & 63] = x[node0 * CC + i];
    __syncthreads();

    int n = tid >> 6, c = tid & 63;
    int node = node0 + n;

    float v = xs[n][c];
    red[tid] = v * v;
    __syncthreads();
    if (c < 32) red[tid] += red[tid + 32]; __syncthreads();
    if (c < 16) red[tid] += red[tid + 16]; __syncthreads();
    if (c < 8)  red[tid] += red[tid + 8];  __syncthreads();
    if (c < 4)  red[tid] += red[tid + 4];  __syncthreads();
    if (c < 2)  red[tid] += red[tid + 2];  __syncthreads();
    if (c < 1)  red[tid] += red[tid + 1];  __syncthreads();
    if (c == 0) g_sq[node] = red[tid];

    float acc = bconv[c];
#pragma unroll
    for (int k = 0; k < CC; k++) acc += xs[n][k] * Ws[c][k];
    g_u[node * CC + c] = acc * dv2f(node);
}

// ---------------- kB: fp32 distance GEMM (128x128 tile, strided micro-tile) ----------------
// D[i,j] = sq[i] + sq[j] - 2 * dot(x_i, x_j)
__global__ __launch_bounds__(256, 2) void kB(const float* __restrict__ x) {
    extern __shared__ float sm[];
    float (*As)[129] = (float (*)[129])sm;                 // [64][129] k-major
    float (*Bs)[129] = (float (*)[129])(sm + 64 * 129);

    int ib = blockIdx.y, jb = blockIdx.x;
    int tid = threadIdx.x;

#pragma unroll
    for (int it = 0; it < 8; it++) {
        int idx = tid + it * 256;       // 0..2047
        int r   = idx >> 4;             // 0..127
        int k4  = (idx & 15) * 4;       // 0..60
        float4 va = *(const float4*)(x + (size_t)(ib * 128 + r) * CC + k4);
        As[k4 + 0][r] = va.x; As[k4 + 1][r] = va.y;
        As[k4 + 2][r] = va.z; As[k4 + 3][r] = va.w;
        float4 vb = *(const float4*)(x + (size_t)(jb * 128 + r) * CC + k4);
        Bs[k4 + 0][r] = vb.x; Bs[k4 + 1][r] = vb.y;
        Bs[k4 + 2][r] = vb.z; Bs[k4 + 3][r] = vb.w;
    }
    __syncthreads();

    int tx = tid & 31;   // cols: tx + 32*j  (conflict-free frag loads)
    int ty = tid >> 5;   // rows: ty*16 + i  (broadcast frag loads)

    float acc[16][4];
#pragma unroll
    for (int i = 0; i < 16; i++)
#pragma unroll
        for (int j = 0; j < 4; j++) acc[i][j] = 0.0f;

#pragma unroll 4
    for (int k = 0; k < 64; k++) {
        float a[16], b[4];
#pragma unroll
        for (int i = 0; i < 16; i++) a[i] = As[k][ty * 16 + i];
#pragma unroll
        for (int j = 0; j < 4; j++)  b[j] = Bs[k][tx + 32 * j];
#pragma unroll
        for (int i = 0; i < 16; i++)
#pragma unroll
            for (int j = 0; j < 4; j++) acc[i][j] += a[i] * b[j];
    }

    float sqi[16], sqj[4];
#pragma unroll
    for (int i = 0; i < 16; i++) sqi[i] = g_sq[ib * 128 + ty * 16 + i];
#pragma unroll
    for (int j = 0; j < 4; j++)  sqj[j] = g_sq[jb * 128 + tx + 32 * j];

#pragma unroll
    for (int i = 0; i < 16; i++) {
        size_t rowoff = (size_t)(ib * 128 + ty * 16 + i) * BNN;
#pragma unroll
        for (int j = 0; j < 4; j++) {
            int col = jb * 128 + tx + 32 * j;
            g_dists[rowoff + col] = sqi[i] + sqj[j] - 2.0f * acc[i][j];
        }
    }
}

// ---------------- kC: per-row top-11 (lexicographic (value,index)) ----------------
__global__ __launch_bounds__(256) void kC() {
    __shared__ float sval[256 * KSEL];
    __shared__ int   sidx[256 * KSEL];
    __shared__ float rv[8];
    __shared__ int   ri[8], ro[8];
    __shared__ int   bo_s;

    int tid = threadIdx.x;
    int row = blockIdx.x;
    float* mv = sval + tid * KSEL;
    int*   mi = sidx + tid * KSEL;

#pragma unroll
    for (int s = 0; s < KSEL; s++) { mv[s] = 3.4e38f; mi[s] = 0x7fffffff; }

    const float* Drow = g_dists + (size_t)row * BNN;
    for (int k2 = 0; k2 < 32; k2++) {
        int j = tid + k2 * 256;
        float v = Drow[j];
        float wv = mv[KSEL - 1]; int wi = mi[KSEL - 1];
        if (v < wv || (v == wv && j < wi)) {
            int p = KSEL - 1;
            while (p > 0) {
                float pv = mv[p - 1]; int pi = mi[p - 1];
                if (v < pv || (v == pv && j < pi)) { mv[p] = pv; mi[p] = pi; p--; }
                else break;
            }
            mv[p] = v; mi[p] = j;
        }
    }
    __syncthreads();

    // merge: 11 rounds of block-wide lexicographic argmin over sorted per-thread lists
    int h = 0;
    int lane = tid & 31, w = tid >> 5;
    for (int m = 0; m < KSEL; m++) {
        float cv = (h < KSEL) ? mv[h] : 3.4e38f;
        int   ci = (h < KSEL) ? mi[h] : 0x7fffffff;
        int   owner = tid;
#pragma unroll
        for (int off = 16; off; off >>= 1) {
            float ov = __shfl_down_sync(0xffffffffu, cv, off);
            int   oi = __shfl_down_sync(0xffffffffu, ci, off);
            int   oo = __shfl_down_sync(0xffffffffu, owner, off);
            if (ov < cv || (ov == cv && oi < ci)) { cv = ov; ci = oi; owner = oo; }
        }
        if (lane == 0) { rv[w] = cv; ri[w] = ci; ro[w] = owner; }
        __syncthreads();
        if (tid == 0) {
            float best = rv[0]; int besti = ri[0]; int besto = ro[0];
            for (int q = 1; q < 8; q++) {
                if (rv[q] < best || (rv[q] == best && ri[q] < besti)) {
                    best = rv[q]; besti = ri[q]; besto = ro[q];
                }
            }
            bo_s = besto;
            g_inds[row * KSEL + m] = besti;
            atomicAdd(&g_de[besti], 1);
        }
        __syncthreads();
        if (tid == bo_s) h++;
    }
}

// ---------------- kScat: scatter u into KNN edge sums ----------------
__global__ __launch_bounds__(256) void kScat() {
    __shared__ int si[4 * KSEL];
    int tid = threadIdx.x;
    int node0 = blockIdx.x * 4;
    if (tid < 4 * KSEL) si[tid] = g_inds[node0 * KSEL + tid];
    __syncthreads();
    int n = tid >> 6, c = tid & 63;
    float uv = g_u[(node0 + n) * CC + c];
#pragma unroll
    for (int m = 0; m < KSEL; m++)
        atomicAdd(&g_sknn[si[n * KSEL + m] * CC + c], uv);
}

// ---------------- kLoc: local edge sums / 25 ----------------
__global__ __launch_bounds__(64) void kLoc() {
    int e = blockIdx.x;           // 0..1567
    int c = threadIdx.x;          // 0..63
    int b  = e / 196, le = e % 196;
    int er = le / 14, ec = le % 14;
    int base = b * NROWS + er * 2 * 32 + ec * 2;
    float s = 0.0f;
#pragma unroll
    for (int dr = 0; dr < 5; dr++)
#pragma unroll
        for (int dc = 0; dc < 5; dc++)
            s += g_u[(base + dr * 32 + dc) * CC + c];
    g_sloc[e * CC + c] = s * (1.0f / 25.0f);
}

// ---------------- kScale: s_knn /= DE ----------------
__global__ void kScale() {
    int i = blockIdx.x * 256 + threadIdx.x;   // 524288
    int j = i >> 6;
    g_sknn[i] *= (1.0f / (float)g_de[j]);
}

// ---------------- kE: gather z + BN stats ----------------
__global__ __launch_bounds__(256) void kE() {
    __shared__ int si[4 * KSEL];
    __shared__ float red[256], red2[256];
    int tid = threadIdx.x;
    int node0 = blockIdx.x * 4;
    if (tid < 4 * KSEL) si[tid] = g_inds[node0 * KSEL + tid];
    __syncthreads();
    int n = tid >> 6, c = tid & 63;
    int node = node0 + n;

    float acc = 0.0f;
#pragma unroll
    for (int m = 0; m < KSEL; m++)
        acc += g_sknn[si[n * KSEL + m] * CC + c];

    // local edges containing this node
    int ln = node & (NROWS - 1);
    int r = ln >> 5, cc2 = ln & 31;
    int b = node >> 10;
    int sr0 = r - 4; if (sr0 < 0) sr0 = 0; sr0 += (sr0 & 1);
    int sr1 = r;     if (sr1 > 26) sr1 = 26; sr1 -= (sr1 & 1);
    int sc0 = cc2 - 4; if (sc0 < 0) sc0 = 0; sc0 += (sc0 & 1);
    int sc1 = cc2;     if (sc1 > 26) sc1 = 26; sc1 -= (sc1 & 1);
    for (int sr = sr0; sr <= sr1; sr += 2)
        for (int sc = sc0; sc <= sc1; sc += 2)
            acc += g_sloc[(b * 196 + (sr >> 1) * 14 + (sc >> 1)) * CC + c];

    float z = acc * dv2f(node);
    g_z[node * CC + c] = z;

    red[tid] = z; red2[tid] = z * z;
    __syncthreads();
    if (tid < 128) { red[tid] += red[tid + 128]; red2[tid] += red2[tid + 128]; }
    __syncthreads();
    if (tid < 64) {
        atomicAdd(&g_stats[tid],      red[tid]  + red[tid + 64]);
        atomicAdd(&g_stats[64 + tid], red2[tid] + red2[tid + 64]);
    }
}

// ---------------- kG: BN + relu + residual ----------------
__global__ void kG(const float* __restrict__ x,
                   const float* __restrict__ gamma,
                   const float* __restrict__ beta,
                   float* __restrict__ out) {
    int i = blockIdx.x * 256 + threadIdx.x;   // 524288
    int c = i & 63;
    float mu  = g_stats[c]      * (1.0f / (float)BNN);
    float ex2 = g_stats[64 + c] * (1.0f / (float)BNN);
    float var = ex2 - mu * mu;
    float rstd = 1.0f / sqrtf(var + 1e-5f);
    float zn = (g_z[i] - mu) * rstd * gamma[c] + beta[c];
    out[i] = fmaxf(zn, 0.0f) + x[i];
}

// ---------------- launch ----------------
extern "C" void kernel_launch(void* const* d_in, const int* in_sizes, int n_in,
                              void* d_out, int out_size) {
    const float* x     = (const float*)d_in[0];
    const float* W     = (const float*)d_in[1];
    const float* bconv = (const float*)d_in[2];
    const float* gamma = (const float*)d_in[3];
    const float* beta  = (const float*)d_in[4];
    float* out = (float*)d_out;

    const int SMEM_B = 2 * 64 * 129 * sizeof(float);   // 66048 B
    cudaFuncSetAttribute(kB, cudaFuncAttributeMaxDynamicSharedMemorySize, SMEM_B);

    kZero <<<2048, 256>>>();
    kA    <<<BNN / 4, 256>>>(x, W, bconv);
    kB    <<<dim3(64, 64), 256, SMEM_B>>>(x);
    kC    <<<BNN, 256>>>();
    kScat <<<BNN / 4, 256>>>();
    kLoc  <<<NLOC, 64>>>();
    kScale<<<2048, 256>>>();
    kE    <<<BNN / 4, 256>>>();
    kG    <<<2048, 256>>>(x, gamma, beta, out);
}

// round 2
// speedup vs baseline: 1.3066x; 1.3066x over previous
#include <cuda_runtime.h>
#include <math.h>

// ---------------- static problem config ----------------
#define BNN   8192      // total nodes (8*1024)
#define CC    64        // channels
#define KSEL  11        // K+1 neighbors
#define NLOC  1568      // 8 * 196 local hyperedges
#define NROWS 1024      // nodes per sample (32*32)

// ---------------- device scratch (no allocations allowed) ----------------
__device__ float g_dists[(size_t)BNN * BNN];   // 256 MB distance matrix
__device__ float g_u[BNN * CC];                // dv2[i] * (x W^T + b)
__device__ float g_sq[BNN];                    // row squared norms
__device__ int   g_inds[BNN * KSEL];           // top-11 neighbor indices
__device__ int   g_de[BNN];                    // KNN edge degrees
__device__ float g_sknn[BNN * CC];             // KNN edge sums (later scaled by 1/DE)
__device__ float g_sloc[NLOC * CC];            // local edge sums / 25
__device__ float g_z[BNN * CC];                // aggregated features
__device__ float g_stats[2 * CC];              // per-channel sum / sumsq

// ---------------- helpers ----------------
__device__ __forceinline__ int covdim(int r) {
    int lo = r - 4; if (lo < 0) lo = 0;
    int hi = r;     if (hi > 26) hi = 26;
    if (hi < lo) return 0;
    return hi / 2 - (lo + 1) / 2 + 1;
}

__device__ __forceinline__ float dv2f(int node) {
    int ln = node & (NROWS - 1);
    int r = ln >> 5, c = ln & 31;
    int deg = covdim(r) * covdim(c);
    return 1.0f / sqrtf((float)(KSEL + deg));
}

// float -> order-preserving uint (total order, matches IEEE compare on non-NaN)
__device__ __forceinline__ unsigned ordkey(float f) {
    unsigned u = __float_as_uint(f);
    return (u & 0x80000000u) ? ~u : (u | 0x80000000u);
}

// ---------------- kZero: clear accumulators ----------------
__global__ void kZero() {
    int i = blockIdx.x * 256 + threadIdx.x;
    if (i < BNN * CC) g_sknn[i] = 0.0f;
    if (i < BNN)      g_de[i]   = 0;
    if (i < 2 * CC)   g_stats[i] = 0.0f;
}

// ---------------- kA: sq norms + u = dv2 * (x W^T + b) ----------------
__global__ __launch_bounds__(256) void kA(const float* __restrict__ x,
                                          const float* __restrict__ W,
                                          const float* __restrict__ bconv) {
    __shared__ float Ws[CC][CC + 1];
    __shared__ float xs[4][CC];
    __shared__ float red[256];
    int tid = threadIdx.x;
    int node0 = blockIdx.x * 4;

    for (int i = tid; i < CC * CC; i += 256) Ws[i >> 6][i & 63] = W[i];
    for (int i = tid; i < 4 * CC; i += 256) xs[i >> 6][i & 63] = x[node0 * CC + i];
    __syncthreads();

    int n = tid >> 6, c = tid & 63;
    int node = node0 + n;

    float v = xs[n][c];
    red[tid] = v * v;
    __syncthreads();
    if (c < 32) red[tid] += red[tid + 32]; __syncthreads();
    if (c < 16) red[tid] += red[tid + 16]; __syncthreads();
    if (c < 8)  red[tid] += red[tid + 8];  __syncthreads();
    if (c < 4)  red[tid] += red[tid + 4];  __syncthreads();
    if (c < 2)  red[tid] += red[tid + 2];  __syncthreads();
    if (c < 1)  red[tid] += red[tid + 1];  __syncthreads();
    if (c == 0) g_sq[node] = red[tid];

    float acc = bconv[c];
#pragma unroll
    for (int k = 0; k < CC; k++) acc += xs[n][k] * Ws[c][k];
    g_u[node * CC + c] = acc * dv2f(node);
}

// ---------------- kB: fp32 distance GEMM (128x128 tile) ----------------
__global__ __launch_bounds__(256, 2) void kB(const float* __restrict__ x) {
    extern __shared__ float sm[];
    float (*As)[129] = (float (*)[129])sm;
    float (*Bs)[129] = (float (*)[129])(sm + 64 * 129);

    int ib = blockIdx.y, jb = blockIdx.x;
    int tid = threadIdx.x;

#pragma unroll
    for (int it = 0; it < 8; it++) {
        int idx = tid + it * 256;
        int r   = idx >> 4;
        int k4  = (idx & 15) * 4;
        float4 va = *(const float4*)(x + (size_t)(ib * 128 + r) * CC + k4);
        As[k4 + 0][r] = va.x; As[k4 + 1][r] = va.y;
        As[k4 + 2][r] = va.z; As[k4 + 3][r] = va.w;
        float4 vb = *(const float4*)(x + (size_t)(jb * 128 + r) * CC + k4);
        Bs[k4 + 0][r] = vb.x; Bs[k4 + 1][r] = vb.y;
        Bs[k4 + 2][r] = vb.z; Bs[k4 + 3][r] = vb.w;
    }
    __syncthreads();

    int tx = tid & 31;
    int ty = tid >> 5;

    float acc[16][4];
#pragma unroll
    for (int i = 0; i < 16; i++)
#pragma unroll
        for (int j = 0; j < 4; j++) acc[i][j] = 0.0f;

#pragma unroll 4
    for (int k = 0; k < 64; k++) {
        float a[16], b[4];
#pragma unroll
        for (int i = 0; i < 16; i++) a[i] = As[k][ty * 16 + i];
#pragma unroll
        for (int j = 0; j < 4; j++)  b[j] = Bs[k][tx + 32 * j];
#pragma unroll
        for (int i = 0; i < 16; i++)
#pragma unroll
            for (int j = 0; j < 4; j++) acc[i][j] += a[i] * b[j];
    }

    float sqi[16], sqj[4];
#pragma unroll
    for (int i = 0; i < 16; i++) sqi[i] = g_sq[ib * 128 + ty * 16 + i];
#pragma unroll
    for (int j = 0; j < 4; j++)  sqj[j] = g_sq[jb * 128 + tx + 32 * j];

#pragma unroll
    for (int i = 0; i < 16; i++) {
        size_t rowoff = (size_t)(ib * 128 + ty * 16 + i) * BNN;
#pragma unroll
        for (int j = 0; j < 4; j++) {
            int col = jb * 128 + tx + 32 * j;
            g_dists[rowoff + col] = sqi[i] + sqj[j] - 2.0f * acc[i][j];
        }
    }
}

// ---------------- kC: warp-per-row top-11, register u64 keys ----------------
__global__ __launch_bounds__(256) void kC() {
    int row  = blockIdx.x * 8 + (threadIdx.x >> 5);
    int lane = threadIdx.x & 31;

    const float4* Drow = (const float4*)(g_dists + (size_t)row * BNN);

    unsigned long long L[KSEL];
#pragma unroll
    for (int s = 0; s < KSEL; s++) L[s] = 0xFFFFFFFFFFFFFFFFull;

#pragma unroll 4
    for (int it = 0; it < 64; it++) {
        int vecidx = lane + (it << 5);            // float4 index
        float4 v = Drow[vecidx];
        unsigned j0 = (unsigned)(vecidx << 2);
        float f[4] = {v.x, v.y, v.z, v.w};
#pragma unroll
        for (int q = 0; q < 4; q++) {
            unsigned long long key =
                ((unsigned long long)ordkey(f[q]) << 32) | (j0 + (unsigned)q);
            if (key < L[KSEL - 1]) {
                L[KSEL - 1] = key;
#pragma unroll
                for (int p = KSEL - 1; p > 0; --p) {
                    unsigned long long a = L[p - 1], b = L[p];
                    bool sw = b < a;
                    L[p - 1] = sw ? b : a;
                    L[p]     = sw ? a : b;
                }
            }
        }
    }

    // merge across lanes: 11 rounds of warp u64-argmin + owner pop
#pragma unroll 1
    for (int m = 0; m < KSEL; m++) {
        unsigned long long k = L[0];
#pragma unroll
        for (int off = 16; off; off >>= 1) {
            unsigned long long o = __shfl_xor_sync(0xffffffffu, k, off);
            if (o < k) k = o;
        }
        if (L[0] == k) {                 // unique owner (idx in low bits)
            int idx = (int)(k & 0xffffffffu);
            g_inds[row * KSEL + m] = idx;
            atomicAdd(&g_de[idx], 1);
#pragma unroll
            for (int p = 0; p < KSEL - 1; p++) L[p] = L[p + 1];
            L[KSEL - 1] = 0xFFFFFFFFFFFFFFFFull;
        }
    }
}

// ---------------- kScat: scatter u into KNN edge sums ----------------
__global__ __launch_bounds__(256) void kScat() {
    __shared__ int si[4 * KSEL];
    int tid = threadIdx.x;
    int node0 = blockIdx.x * 4;
    if (tid < 4 * KSEL) si[tid] = g_inds[node0 * KSEL + tid];
    __syncthreads();
    int n = tid >> 6, c = tid & 63;
    float uv = g_u[(node0 + n) * CC + c];
#pragma unroll
    for (int m = 0; m < KSEL; m++)
        atomicAdd(&g_sknn[si[n * KSEL + m] * CC + c], uv);
}

// ---------------- kLoc: local edge sums / 25 ----------------
__global__ __launch_bounds__(64) void kLoc() {
    int e = blockIdx.x;
    int c = threadIdx.x;
    int b  = e / 196, le = e % 196;
    int er = le / 14, ec = le % 14;
    int base = b * NROWS + er * 2 * 32 + ec * 2;
    float s = 0.0f;
#pragma unroll
    for (int dr = 0; dr < 5; dr++)
#pragma unroll
        for (int dc = 0; dc < 5; dc++)
            s += g_u[(base + dr * 32 + dc) * CC + c];
    g_sloc[e * CC + c] = s * (1.0f / 25.0f);
}

// ---------------- kScale: s_knn /= DE ----------------
__global__ void kScale() {
    int i = blockIdx.x * 256 + threadIdx.x;
    int j = i >> 6;
    g_sknn[i] *= (1.0f / (float)g_de[j]);
}

// ---------------- kE: gather z + BN stats ----------------
__global__ __launch_bounds__(256) void kE() {
    __shared__ int si[4 * KSEL];
    __shared__ float red[256], red2[256];
    int tid = threadIdx.x;
    int node0 = blockIdx.x * 4;
    if (tid < 4 * KSEL) si[tid] = g_inds[node0 * KSEL + tid];
    __syncthreads();
    int n = tid >> 6, c = tid & 63;
    int node = node0 + n;

    float acc = 0.0f;
#pragma unroll
    for (int m = 0; m < KSEL; m++)
        acc += g_sknn[si[n * KSEL + m] * CC + c];

    int ln = node & (NROWS - 1);
    int r = ln >> 5, cc2 = ln & 31;
    int b = node >> 10;
    int sr0 = r - 4; if (sr0 < 0) sr0 = 0; sr0 += (sr0 & 1);
    int sr1 = r;     if (sr1 > 26) sr1 = 26; sr1 -= (sr1 & 1);
    int sc0 = cc2 - 4; if (sc0 < 0) sc0 = 0; sc0 += (sc0 & 1);
    int sc1 = cc2;     if (sc1 > 26) sc1 = 26; sc1 -= (sc1 & 1);
    for (int sr = sr0; sr <= sr1; sr += 2)
        for (int sc = sc0; sc <= sc1; sc += 2)
            acc += g_sloc[(b * 196 + (sr >> 1) * 14 + (sc >> 1)) * CC + c];

    float z = acc * dv2f(node);
    g_z[node * CC + c] = z;

    red[tid] = z; red2[tid] = z * z;
    __syncthreads();
    if (tid < 128) { red[tid] += red[tid + 128]; red2[tid] += red2[tid + 128]; }
    __syncthreads();
    if (tid < 64) {
        atomicAdd(&g_stats[tid],      red[tid]  + red[tid + 64]);
        atomicAdd(&g_stats[64 + tid], red2[tid] + red2[tid + 64]);
    }
}

// ---------------- kG: BN + relu + residual ----------------
__global__ void kG(const float* __restrict__ x,
                   const float* __restrict__ gamma,
                   const float* __restrict__ beta,
                   float* __restrict__ out) {
    int i = blockIdx.x * 256 + threadIdx.x;
    int c = i & 63;
    float mu  = g_stats[c]      * (1.0f / (float)BNN);
    float ex2 = g_stats[64 + c] * (1.0f / (float)BNN);
    float var = ex2 - mu * mu;
    float rstd = 1.0f / sqrtf(var + 1e-5f);
    float zn = (g_z[i] - mu) * rstd * gamma[c] + beta[c];
    out[i] = fmaxf(zn, 0.0f) + x[i];
}

// ---------------- launch ----------------
extern "C" void kernel_launch(void* const* d_in, const int* in_sizes, int n_in,
                              void* d_out, int out_size) {
    const float* x     = (const float*)d_in[0];
    const float* W     = (const float*)d_in[1];
    const float* bconv = (const float*)d_in[2];
    const float* gamma = (const float*)d_in[3];
    const float* beta  = (const float*)d_in[4];
    float* out = (float*)d_out;

    const int SMEM_B = 2 * 64 * 129 * sizeof(float);
    cudaFuncSetAttribute(kB, cudaFuncAttributeMaxDynamicSharedMemorySize, SMEM_B);

    kZero <<<2048, 256>>>();
    kA    <<<BNN / 4, 256>>>(x, W, bconv);
    kB    <<<dim3(64, 64), 256, SMEM_B>>>(x);
    kC    <<<BNN / 8, 256>>>();
    kScat <<<BNN / 4, 256>>>();
    kLoc  <<<NLOC, 64>>>();
    kScale<<<2048, 256>>>();
    kE    <<<BNN / 4, 256>>>();
    kG    <<<2048, 256>>>(x, gamma, beta, out);
}